// round 6
// baseline (speedup 1.0000x reference)
#include <cuda_runtime.h>
#include <cuda_bf16.h>

// ---------------- problem dims ----------------
#define BDIM  64
#define SDIM  2048
#define EDIM  1024
#define DDIM  1024
#define SYNCD 512
#define MDIM  32
#define NHEADS 16
#define DH    64
#define SYNH  2048
#define TRH   64

typedef unsigned int uint32;

// ---------------- scratch (static device globals; no allocation) ----------------
__device__ __nv_bfloat16 g_kv [(size_t)BDIM * SDIM * EDIM];   // x_context + zH, bf16
__device__ __nv_bfloat16 g_pk [(size_t)BDIM * SDIM * EDIM];   // phi(k)
__device__ __nv_bfloat16 g_v  [(size_t)BDIM * SDIM * EDIM];   // v
__device__ __nv_bfloat16 g_wkv[(size_t)EDIM * 2048];          // [k][n]: n<1024 wk, else wv
__device__ float g_bias2[2048];                                // bk | bv
__device__ float g_q    [BDIM * EDIM];
__device__ float g_pq   [BDIM * EDIM];
__device__ float g_kvstate[(size_t)BDIM * NHEADS * DH * DH];  // [b*16+h][dk][dv]
__device__ float g_ksum [BDIM * NHEADS * DH];
__device__ float g_pre  [BDIM * 2048];                         // [attn_out | activated_zL]
__device__ float g_hidden[BDIM * SYNH];
__device__ float g_state[BDIM * DDIM];

// ---------------- helpers ----------------
__device__ __forceinline__ float phi_f(float x) {
    // elu(x)+1
    return x > 0.f ? x + 1.f : __expf(x);
}

__device__ __forceinline__ void mma16816(float* d, const uint32* a, const uint32* b) {
    asm volatile(
        "mma.sync.aligned.m16n8k16.row.col.f32.bf16.bf16.f32 "
        "{%0,%1,%2,%3},{%4,%5,%6,%7},{%8,%9},{%0,%1,%2,%3};\n"
        : "+f"(d[0]), "+f"(d[1]), "+f"(d[2]), "+f"(d[3])
        : "r"(a[0]), "r"(a[1]), "r"(a[2]), "r"(a[3]), "r"(b[0]), "r"(b[1]));
}

// ---------------- pass 1a: pack weights (wk|wv -> bf16, biases) ----------------
__global__ void pack_w_kernel(const float* __restrict__ wk, const float* __restrict__ wv,
                              const float* __restrict__ bk, const float* __restrict__ bv) {
    int i = blockIdx.x * blockDim.x + threadIdx.x;  // 0 .. 2M-1
    if (i < EDIM * 2048) {
        int k = i >> 11, n = i & 2047;
        float v = (n < 1024) ? wk[k * 1024 + n] : wv[k * 1024 + (n - 1024)];
        g_wkv[i] = __float2bfloat16(v);
    }
    if (i < 2048) {
        g_bias2[i] = (i < 1024) ? bk[i] : bv[i - 1024];
    }
}

// ---------------- pass 1b: kv = x_context + zH -> bf16 ----------------
__global__ void convert_kv_kernel(const float* __restrict__ x, const float* __restrict__ zH) {
    size_t i4 = (size_t)blockIdx.x * blockDim.x + threadIdx.x;  // per float4
    size_t e0 = i4 * 4;
    int e = (int)(e0 & 1023);
    int b = (int)(e0 >> 21);  // S*E = 2^21
    float4 xv = ((const float4*)x)[i4];
    float4 zv = *(const float4*)&zH[b * 1024 + e];
    __nv_bfloat162 lo, hi;
    lo.x = __float2bfloat16(xv.x + zv.x); lo.y = __float2bfloat16(xv.y + zv.y);
    hi.x = __float2bfloat16(xv.z + zv.z); hi.y = __float2bfloat16(xv.w + zv.w);
    ((__nv_bfloat162*)g_kv)[i4 * 2]     = lo;
    ((__nv_bfloat162*)g_kv)[i4 * 2 + 1] = hi;
}

// ---------------- generic small GEMM: C[64][N] = act(A[64][K] @ W[K][N] + bias) ----------------
// act: 0 = none, 1 = relu, 2 = phi (elu+1)
__global__ void __launch_bounds__(256) gemm64_kernel(
    const float* __restrict__ A, int K,
    const float* __restrict__ W, const float* __restrict__ bias,
    float* __restrict__ C, int N, int act) {
    __shared__ float sA[64][33];
    __shared__ float sW[32][65];
    int tid = threadIdx.x;
    int g = tid >> 6, nn = tid & 63;
    int n0 = blockIdx.x * 64;
    float acc[16];
#pragma unroll
    for (int i = 0; i < 16; i++) acc[i] = 0.f;

    for (int kc = 0; kc < K; kc += 32) {
        for (int idx = tid; idx < 2048; idx += 256) {
            int bb = idx >> 5, kk = idx & 31;
            sA[bb][kk] = A[(size_t)bb * K + kc + kk];
        }
        for (int idx = tid; idx < 2048; idx += 256) {
            int kk = idx >> 6, n_ = idx & 63;
            sW[kk][n_] = W[(size_t)(kc + kk) * N + n0 + n_];
        }
        __syncthreads();
#pragma unroll 8
        for (int kk = 0; kk < 32; kk++) {
            float w = sW[kk][nn];
#pragma unroll
            for (int bl = 0; bl < 16; bl++)
                acc[bl] += sA[g * 16 + bl][kk] * w;
        }
        __syncthreads();
    }
    float bvv = bias ? bias[n0 + nn] : 0.f;
#pragma unroll
    for (int bl = 0; bl < 16; bl++) {
        float v = acc[bl] + bvv;
        if (act == 1) v = fmaxf(v, 0.f);
        else if (act == 2) v = phi_f(v);
        C[(size_t)(g * 16 + bl) * N + n0 + nn] = v;
    }
}

// ---------------- pass 2: big GEMM  out = [phi(kv@wk+bk) | kv@wv+bv]  (bf16 mma) ----------------
// grid = (16 n-tiles, 1024 m-tiles), 256 threads
__global__ void __launch_bounds__(256) gemm_kv_kernel() {
    __shared__ __nv_bfloat16 sA[128][40];  // A tile row-major [m][k]  (stride 80B, 16B aligned)
    __shared__ __nv_bfloat16 sW[128][34];  // W tile transposed [n][k] (stride 68B, odd banks)

    int tid = threadIdx.x;
    int warp = tid >> 5, lane = tid & 31;
    int gid = lane >> 2, tig = lane & 3;
    int warp_m = warp >> 1, warp_n = warp & 1;
    int n0 = blockIdx.x * 128;
    int m0 = blockIdx.y * 128;

    float acc[2][8][4];
#pragma unroll
    for (int mi = 0; mi < 2; mi++)
#pragma unroll
        for (int ni = 0; ni < 8; ni++)
#pragma unroll
            for (int q = 0; q < 4; q++) acc[mi][ni][q] = 0.f;

    for (int kc = 0; kc < 1024; kc += 32) {
        // A: 128x32 bf16 (512 uint4)
#pragma unroll
        for (int t = 0; t < 2; t++) {
            int i = tid + t * 256;
            int row = i >> 2, seg = i & 3;
            uint4 v = *(const uint4*)(g_kv + ((size_t)(m0 + row)) * 1024 + kc + seg * 8);
            *(uint4*)&sA[row][seg * 8] = v;
        }
        // W: 32x128 -> transposed store (2048 uint reads = 2 bf16 each)
#pragma unroll
        for (int t = 0; t < 8; t++) {
            int i = tid + t * 256;
            int kk = i >> 6, nn2 = i & 63;
            uint32 v = *(const uint32*)(g_wkv + (size_t)(kc + kk) * 2048 + n0 + nn2 * 2);
            __nv_bfloat162 p = *(__nv_bfloat162*)&v;
            sW[nn2 * 2][kk] = p.x;
            sW[nn2 * 2 + 1][kk] = p.y;
        }
        __syncthreads();

#pragma unroll
        for (int ks = 0; ks < 32; ks += 16) {
            uint32 afr[2][4], bfr[8][2];
#pragma unroll
            for (int mi = 0; mi < 2; mi++) {
                int r = warp_m * 32 + mi * 16;
                afr[mi][0] = *(uint32*)&sA[r + gid][ks + tig * 2];
                afr[mi][1] = *(uint32*)&sA[r + gid + 8][ks + tig * 2];
                afr[mi][2] = *(uint32*)&sA[r + gid][ks + tig * 2 + 8];
                afr[mi][3] = *(uint32*)&sA[r + gid + 8][ks + tig * 2 + 8];
            }
#pragma unroll
            for (int ni = 0; ni < 8; ni++) {
                int n = warp_n * 64 + ni * 8;
                bfr[ni][0] = *(uint32*)&sW[n + gid][ks + tig * 2];
                bfr[ni][1] = *(uint32*)&sW[n + gid][ks + tig * 2 + 8];
            }
#pragma unroll
            for (int mi = 0; mi < 2; mi++)
#pragma unroll
                for (int ni = 0; ni < 8; ni++)
                    mma16816(acc[mi][ni], afr[mi], bfr[ni]);
        }
        __syncthreads();
    }

    // epilogue: bias (+phi on k-half), write bf16
    bool is_k = (n0 < 1024);
    __nv_bfloat16* dst = is_k ? g_pk : g_v;
    int cbase = is_k ? n0 : (n0 - 1024);
#pragma unroll
    for (int mi = 0; mi < 2; mi++) {
        int r = m0 + warp_m * 32 + mi * 16 + gid;
#pragma unroll
        for (int ni = 0; ni < 8; ni++) {
            int cl = warp_n * 64 + ni * 8 + tig * 2;
            float b0 = g_bias2[n0 + cl], b1 = g_bias2[n0 + cl + 1];
            float v00 = acc[mi][ni][0] + b0, v01 = acc[mi][ni][1] + b1;
            float v10 = acc[mi][ni][2] + b0, v11 = acc[mi][ni][3] + b1;
            if (is_k) { v00 = phi_f(v00); v01 = phi_f(v01); v10 = phi_f(v10); v11 = phi_f(v11); }
            __nv_bfloat162 p0, p1;
            p0.x = __float2bfloat16(v00); p0.y = __float2bfloat16(v01);
            p1.x = __float2bfloat16(v10); p1.y = __float2bfloat16(v11);
            *(__nv_bfloat162*)(dst + (size_t)r * 1024 + cbase + cl)       = p0;
            *(__nv_bfloat162*)(dst + (size_t)(r + 8) * 1024 + cbase + cl) = p1;
        }
    }
}

// ---------------- pass 3: kv_state[b,h] = pk^T @ v  (K = S), ksum = colsum(pk) ----------------
// grid = B*H = 1024, 128 threads (4 warps)
__global__ void __launch_bounds__(128) kvstate_kernel() {
    __shared__ __nv_bfloat16 sPk[64][34];  // transposed: [dk][s]
    __shared__ __nv_bfloat16 sV [64][34];  // transposed: [dv][s]

    int tid = threadIdx.x;
    int bh = blockIdx.x;
    int bb = bh >> 4, h = bh & 15;
    int warp = tid >> 5, lane = tid & 31, gid = lane >> 2, tig = lane & 3;

    float acc[8][4];
#pragma unroll
    for (int ni = 0; ni < 8; ni++)
#pragma unroll
        for (int q = 0; q < 4; q++) acc[ni][q] = 0.f;
    float ksum = 0.f;

    size_t base = ((size_t)bb * 2048) * 1024 + h * 64;
    for (int sc = 0; sc < 2048; sc += 32) {
#pragma unroll
        for (int t = 0; t < 16; t++) {
            int i = tid + t * 128;  // 0..2047
            int ss = i >> 6, dk = i & 63;
            size_t gi = base + (size_t)(sc + ss) * 1024 + dk;
            sPk[dk][ss] = g_pk[gi];
            sV [dk][ss] = g_v [gi];
        }
        __syncthreads();
        if (tid < 64) {
#pragma unroll
            for (int ss = 0; ss < 32; ss++) ksum += __bfloat162float(sPk[tid][ss]);
        }
#pragma unroll
        for (int ks = 0; ks < 32; ks += 16) {
            uint32 afr[4], bfr[8][2];
            int r = warp * 16;
            afr[0] = *(uint32*)&sPk[r + gid][ks + tig * 2];
            afr[1] = *(uint32*)&sPk[r + gid + 8][ks + tig * 2];
            afr[2] = *(uint32*)&sPk[r + gid][ks + tig * 2 + 8];
            afr[3] = *(uint32*)&sPk[r + gid + 8][ks + tig * 2 + 8];
#pragma unroll
            for (int ni = 0; ni < 8; ni++) {
                bfr[ni][0] = *(uint32*)&sV[ni * 8 + gid][ks + tig * 2];
                bfr[ni][1] = *(uint32*)&sV[ni * 8 + gid][ks + tig * 2 + 8];
            }
#pragma unroll
            for (int ni = 0; ni < 8; ni++) mma16816(acc[ni], afr, bfr[ni]);
        }
        __syncthreads();
    }

    float* out = g_kvstate + (size_t)bh * 4096;
#pragma unroll
    for (int ni = 0; ni < 8; ni++) {
        int col = ni * 8 + tig * 2;
        int row = warp * 16 + gid;
        out[row * 64 + col]           = acc[ni][0];
        out[row * 64 + col + 1]       = acc[ni][1];
        out[(row + 8) * 64 + col]     = acc[ni][2];
        out[(row + 8) * 64 + col + 1] = acc[ni][3];
    }
    if (tid < 64) g_ksum[(size_t)bh * 64 + tid] = ksum;
}

// ---------------- pass 4: attn readout + wo projection + assemble pre ----------------
// grid = B, 256 threads
__global__ void __launch_bounds__(256) attn_kernel(const float* __restrict__ wo,
                                                   const float* __restrict__ bo,
                                                   const float* __restrict__ zL) {
    __shared__ float s_pq[1024];
    __shared__ float s_attn[1024];
    __shared__ float s_den[16];
    int bb = blockIdx.x, tid = threadIdx.x;

    for (int i = tid; i < 1024; i += 256) s_pq[i] = g_pq[bb * 1024 + i];
    __syncthreads();
    if (tid < 16) {
        const float* ks = g_ksum + ((size_t)bb * 16 + tid) * 64;
        float d = 0.f;
#pragma unroll 8
        for (int k = 0; k < 64; k++) d += s_pq[tid * 64 + k] * ks[k];
        s_den[tid] = d + 1e-6f;
    }
    __syncthreads();
#pragma unroll
    for (int j = 0; j < 4; j++) {
        int e = tid + j * 256;
        int h = e >> 6, dv = e & 63;
        const float* kvs = g_kvstate + (((size_t)bb * 16 + h) * 64) * 64 + dv;
        float num = 0.f;
#pragma unroll 8
        for (int dk = 0; dk < 64; dk++) num += s_pq[h * 64 + dk] * kvs[dk * 64];
        s_attn[e] = num / s_den[h];
    }
    __syncthreads();
#pragma unroll
    for (int j = 0; j < 4; j++) {
        int o = tid + j * 256;
        float acc = bo[o];
#pragma unroll 4
        for (int i = 0; i < 1024; i++) acc += s_attn[i] * wo[(size_t)i * 1024 + o];
        g_pre[(size_t)bb * 2048 + o] = acc;
        g_pre[(size_t)bb * 2048 + 1024 + o] = zL[(size_t)bb * 1024 + o];
    }
}

// ---------------- pass 6: trace shift + trace processor -> both outputs ----------------
// grid = 65536/64 = 1024, 256 threads
__global__ void __launch_bounds__(256) trace_kernel(const float* __restrict__ zt,
                                                    const float* __restrict__ w1,
                                                    const float* __restrict__ b1,
                                                    const float* __restrict__ w2,
                                                    const float* __restrict__ b2p,
                                                    float* __restrict__ out) {
    __shared__ float sT[64][33];
    __shared__ float sW1[32][64];
    __shared__ float sB1[64];
    __shared__ float sW2[64];
    __shared__ float sRed[4][64];
    int tid = threadIdx.x;
    int r0 = blockIdx.x * 64;
    float* out_act = out;
    float* out_tr = out + BDIM * DDIM;

    for (int idx = tid; idx < 2048; idx += 256) {
        int rr = idx >> 5, mm = idx & 31;
        float v = (mm < 31) ? zt[(size_t)(r0 + rr) * 32 + mm + 1] : g_state[r0 + rr];
        sT[rr][mm] = v;
        out_tr[(size_t)(r0 + rr) * 32 + mm] = v;
    }
    for (int idx = tid; idx < 2048; idx += 256) {
        int m = idx >> 6, hh = idx & 63;
        sW1[m][hh] = w1[idx];
    }
    if (tid < 64) { sB1[tid] = b1[tid]; sW2[tid] = w2[tid]; }
    __syncthreads();

    int rr = tid & 63, part = tid >> 6;
    float acc = 0.f;
#pragma unroll
    for (int hi = 0; hi < 16; hi++) {
        int hh = part * 16 + hi;
        float hs = sB1[hh];
#pragma unroll
        for (int m = 0; m < 32; m++) hs += sT[rr][m] * sW1[m][hh];
        acc += fmaxf(hs, 0.f) * sW2[hh];
    }
    sRed[part][rr] = acc;
    __syncthreads();
    if (tid < 64)
        out_act[r0 + tid] = sRed[0][tid] + sRed[1][tid] + sRed[2][tid] + sRed[3][tid] + b2p[0];
}

// ---------------- launch ----------------
extern "C" void kernel_launch(void* const* d_in, const int* in_sizes, int n_in,
                              void* d_out, int out_size) {
    (void)in_sizes; (void)n_in; (void)out_size;
    const float* zL  = (const float*)d_in[0];
    const float* zt  = (const float*)d_in[1];
    const float* zH  = (const float*)d_in[2];
    const float* x   = (const float*)d_in[3];
    const float* sy  = (const float*)d_in[4];
    const float* qpw = (const float*)d_in[5];
    const float* qpb = (const float*)d_in[6];
    const float* wq  = (const float*)d_in[7];
    const float* bq  = (const float*)d_in[8];
    const float* wk  = (const float*)d_in[9];
    const float* bk  = (const float*)d_in[10];
    const float* wv  = (const float*)d_in[11];
    const float* bv  = (const float*)d_in[12];
    const float* wo  = (const float*)d_in[13];
    const float* bo  = (const float*)d_in[14];
    const float* sw1 = (const float*)d_in[15];
    const float* sb1 = (const float*)d_in[16];
    const float* sw2 = (const float*)d_in[17];
    const float* sb2 = (const float*)d_in[18];
    const float* tw1 = (const float*)d_in[19];
    const float* tb1 = (const float*)d_in[20];
    const float* tw2 = (const float*)d_in[21];
    const float* tb2 = (const float*)d_in[22];
    float* out = (float*)d_out;

    float *p_q, *p_pq, *p_pre, *p_hidden, *p_state;
    cudaGetSymbolAddress((void**)&p_q,      g_q);
    cudaGetSymbolAddress((void**)&p_pq,     g_pq);
    cudaGetSymbolAddress((void**)&p_pre,    g_pre);
    cudaGetSymbolAddress((void**)&p_hidden, g_hidden);
    cudaGetSymbolAddress((void**)&p_state,  g_state);

    // weights / activations to bf16
    pack_w_kernel<<<8192, 256>>>(wk, wv, bk, bv);
    convert_kv_kernel<<<131072, 256>>>(x, zH);

    // q path: q = sync@qp_w + qp_b ; pq = phi(q@wq + bq)
    gemm64_kernel<<<16, 256>>>(sy, SYNCD, qpw, qpb, p_q, 1024, 0);
    gemm64_kernel<<<16, 256>>>(p_q, 1024, wq, bq, p_pq, 1024, 2);

    // big K/V projection GEMM (bf16 mma) + phi epilogue
    gemm_kv_kernel<<<dim3(16, 1024), 256>>>();

    // linear-attention state
    kvstate_kernel<<<1024, 128>>>();

    // attention readout + wo + assemble pre = [attn_out | activated_zL]
    attn_kernel<<<64, 256>>>(wo, bo, zL);

    // synapse MLP
    gemm64_kernel<<<32, 256>>>(p_pre, 2048, sw1, sb1, p_hidden, SYNH, 1);
    gemm64_kernel<<<16, 256>>>(p_hidden, SYNH, sw2, sb2, p_state, DDIM, 0);

    // trace update + processor -> writes both outputs
    trace_kernel<<<1024, 256>>>(zt, tw1, tb1, tw2, tb2, out);
}

// round 10
// speedup vs baseline: 1.8084x; 1.8084x over previous
#include <cuda_runtime.h>
#include <cuda_bf16.h>
#include <cstdint>

// ---------------- problem dims ----------------
#define BDIM  64
#define SDIM  2048
#define EDIM  1024
#define DDIM  1024
#define SYNCD 512
#define MDIM  32
#define NHEADS 16
#define DH    64
#define SYNH  2048
#define TRH   64

typedef unsigned int uint32;

// ---------------- scratch (static device globals; no allocation) ----------------
__device__ __nv_bfloat16 g_kv  [(size_t)BDIM * SDIM * EDIM];  // x_context + zH, bf16
__device__ __nv_bfloat16 g_pk  [(size_t)BDIM * SDIM * EDIM];  // phi(k)
__device__ __nv_bfloat16 g_v   [(size_t)BDIM * SDIM * EDIM];  // v
__device__ __nv_bfloat16 g_wkvT[(size_t)2048 * EDIM];         // transposed: [n][k], n<1024 wk else wv
__device__ float g_bias2[2048];                               // bk | bv
__device__ float g_q    [BDIM * EDIM];
__device__ float g_pq   [BDIM * EDIM];
__device__ float g_kvstate[(size_t)BDIM * NHEADS * DH * DH];  // [b*16+h][dk][dv]
__device__ float g_ksum [BDIM * NHEADS * DH];
__device__ float g_attn [BDIM * EDIM];
__device__ float g_pre  [BDIM * 2048];                        // [attn_out | activated_zL]
__device__ float g_hidden[BDIM * SYNH];
__device__ float g_state[BDIM * DDIM];
__device__ float g_partial[(size_t)8 * 64 * 2048];            // split-K partials

// ---------------- helpers ----------------
__device__ __forceinline__ float phi_f(float x) { return x > 0.f ? x + 1.f : __expf(x); }

__device__ __forceinline__ uint32 smem_u32(const void* p) {
    return (uint32)__cvta_generic_to_shared(p);
}

#define CP_ASYNC16(dst, src) \
    asm volatile("cp.async.cg.shared.global [%0], [%1], 16;" :: "r"(dst), "l"(src) : "memory")
#define CP_COMMIT() asm volatile("cp.async.commit_group;" ::: "memory")
#define CP_WAIT(n)  asm volatile("cp.async.wait_group %0;" :: "n"(n) : "memory")

#define LDSM4(r0, r1, r2, r3, addr) \
    asm volatile("ldmatrix.sync.aligned.m8n8.x4.shared.b16 {%0,%1,%2,%3}, [%4];" \
                 : "=r"(r0), "=r"(r1), "=r"(r2), "=r"(r3) : "r"(addr))

__device__ __forceinline__ void mma16816(float* d, const uint32* a, const uint32* b) {
    asm volatile(
        "mma.sync.aligned.m16n8k16.row.col.f32.bf16.bf16.f32 "
        "{%0,%1,%2,%3},{%4,%5,%6,%7},{%8,%9},{%0,%1,%2,%3};\n"
        : "+f"(d[0]), "+f"(d[1]), "+f"(d[2]), "+f"(d[3])
        : "r"(a[0]), "r"(a[1]), "r"(a[2]), "r"(a[3]), "r"(b[0]), "r"(b[1]));
}

// ---------------- pack: transpose wk|wv -> g_wkvT[n][k] bf16 ----------------
__global__ void __launch_bounds__(256) pack_wT_kernel(const float* __restrict__ wk,
                                                      const float* __restrict__ wv) {
    __shared__ float tile[32][33];
    int tx = threadIdx.x & 31, ty = threadIdx.x >> 5;  // 32 x 8
    int n_glob0 = blockIdx.x * 32;
    int k0 = blockIdx.y * 32;
    const float* src = (n_glob0 < 1024) ? wk : wv;
    int ncol0 = (n_glob0 < 1024) ? n_glob0 : (n_glob0 - 1024);
#pragma unroll
    for (int j = 0; j < 32; j += 8) {
        int k = k0 + ty + j;
        tile[ty + j][tx] = src[(size_t)k * 1024 + ncol0 + tx];
    }
    __syncthreads();
#pragma unroll
    for (int j = 0; j < 32; j += 8) {
        int n = n_glob0 + ty + j;
        int k = k0 + tx;
        g_wkvT[(size_t)n * 1024 + k] = __float2bfloat16(tile[tx][ty + j]);
    }
}

__global__ void biases_kernel(const float* __restrict__ bk, const float* __restrict__ bv) {
    int i = blockIdx.x * blockDim.x + threadIdx.x;
    if (i < 2048) g_bias2[i] = (i < 1024) ? bk[i] : bv[i - 1024];
}

// ---------------- kv = x_context + zH -> bf16 ----------------
__global__ void convert_kv_kernel(const float* __restrict__ x, const float* __restrict__ zH) {
    size_t i4 = (size_t)blockIdx.x * blockDim.x + threadIdx.x;
    size_t e0 = i4 * 4;
    int e = (int)(e0 & 1023);
    int b = (int)(e0 >> 21);
    float4 xv = ((const float4*)x)[i4];
    float4 zv = *(const float4*)&zH[b * 1024 + e];
    __nv_bfloat162 lo, hi;
    lo.x = __float2bfloat16(xv.x + zv.x); lo.y = __float2bfloat16(xv.y + zv.y);
    hi.x = __float2bfloat16(xv.z + zv.z); hi.y = __float2bfloat16(xv.w + zv.w);
    ((__nv_bfloat162*)g_kv)[i4 * 2]     = lo;
    ((__nv_bfloat162*)g_kv)[i4 * 2 + 1] = hi;
}

// ---------------- split-K small GEMM: partial[split] = A[64][Kc-slice] @ W ----------------
__global__ void __launch_bounds__(256) gemm_splitk_kernel(
    const float* __restrict__ A, int K, int Kc,
    const float* __restrict__ W, float* __restrict__ partial, int N) {
    __shared__ float sA[64][33];
    __shared__ float sW[32][65];
    int tid = threadIdx.x;
    int g = tid >> 6, nn = tid & 63;
    int n0 = blockIdx.x * 64;
    int k0 = blockIdx.y * Kc;
    float acc[16];
#pragma unroll
    for (int i = 0; i < 16; i++) acc[i] = 0.f;

    for (int kc = k0; kc < k0 + Kc; kc += 32) {
        for (int idx = tid; idx < 2048; idx += 256) {
            int bb = idx >> 5, kk = idx & 31;
            sA[bb][kk] = A[(size_t)bb * K + kc + kk];
        }
        for (int idx = tid; idx < 2048; idx += 256) {
            int kk = idx >> 6, n_ = idx & 63;
            sW[kk][n_] = W[(size_t)(kc + kk) * N + n0 + n_];
        }
        __syncthreads();
#pragma unroll 8
        for (int kk = 0; kk < 32; kk++) {
            float w = sW[kk][nn];
#pragma unroll
            for (int bl = 0; bl < 16; bl++)
                acc[bl] += sA[g * 16 + bl][kk] * w;
        }
        __syncthreads();
    }
    float* out = partial + (size_t)blockIdx.y * 64 * N;
#pragma unroll
    for (int bl = 0; bl < 16; bl++)
        out[(size_t)(g * 16 + bl) * N + n0 + nn] = acc[bl];
}

// act: 0 none, 1 relu, 2 phi
__global__ void reduce_act_kernel(const float* __restrict__ partial, int nsplit,
                                  const float* __restrict__ bias,
                                  float* __restrict__ out, int N, int out_stride, int act) {
    int i = blockIdx.x * blockDim.x + threadIdx.x;
    if (i >= 64 * N) return;
    int b = i / N, n = i - b * N;
    float acc = bias ? bias[n] : 0.f;
    for (int s = 0; s < nsplit; s++) acc += partial[(size_t)s * 64 * N + i];
    if (act == 1) acc = fmaxf(acc, 0.f);
    else if (act == 2) acc = phi_f(acc);
    out[(size_t)b * out_stride + n] = acc;
}

// ---------------- big GEMM (pipelined HMMA): [phi(kv@wk+bk) | kv@wv+bv] ----------------
// CTA tile 128(M) x 256(N), k-chunks of 32, 4-stage cp.async, ldmatrix operands.
// 8 warps, each computes 64x64 (warp grid 2M x 4N).
#define KV_TM 128
#define KV_TN 256
#define KV_SA_BYTES (128 * 80)                 // row stride 80B = 32 bf16 + 16B pad
#define KV_SB_BYTES (256 * 80)
#define KV_STAGE_BYTES (KV_SA_BYTES + KV_SB_BYTES)   // 30720
#define KV_SMEM_BYTES (4 * KV_STAGE_BYTES)           // 122880

__global__ void __launch_bounds__(256, 1) gemm_kv_mma_kernel() {
    extern __shared__ char sm_raw[];
    uint32 base = smem_u32(sm_raw);
    int tid = threadIdx.x, warp = tid >> 5, lane = tid & 31;
    int gid = lane >> 2, tig = lane & 3;
    int wm = warp >> 2, wn = warp & 3;             // 2 x 4 warp grid
    int n0 = blockIdx.x * KV_TN, m0 = blockIdx.y * KV_TM;

    const __nv_bfloat16* baseA = g_kv   + (size_t)m0 * 1024;
    const __nv_bfloat16* baseB = g_wkvT + (size_t)n0 * 1024;

    float acc[4][8][4];
#pragma unroll
    for (int mi = 0; mi < 4; mi++)
#pragma unroll
        for (int ni = 0; ni < 8; ni++)
#pragma unroll
            for (int q = 0; q < 4; q++) acc[mi][ni][q] = 0.f;

    auto load_chunk = [&](int c, int s) {
        uint32 sa = base + s * KV_STAGE_BYTES;
        uint32 sb = sa + KV_SA_BYTES;
        int kc = c * 32;
#pragma unroll
        for (int t = 0; t < 2; t++) {
            int i = tid + t * 256;                 // 0..511
            int row = i >> 2, seg = i & 3;
            CP_ASYNC16(sa + row * 80 + seg * 16,
                       baseA + (size_t)row * 1024 + kc + seg * 8);
        }
#pragma unroll
        for (int t = 0; t < 4; t++) {
            int i = tid + t * 256;                 // 0..1023
            int row = i >> 2, seg = i & 3;
            CP_ASYNC16(sb + row * 80 + seg * 16,
                       baseB + (size_t)row * 1024 + kc + seg * 8);
        }
    };

    load_chunk(0, 0); CP_COMMIT();
    load_chunk(1, 1); CP_COMMIT();
    load_chunk(2, 2); CP_COMMIT();

    // ldmatrix per-lane address offsets (within a stage)
    int rowA_off = (wm * 64 + (lane & 15)) * 80 + (lane >> 4) * 16;
    int rowB_off = (wn * 64 + (lane & 7) + ((lane >> 4) << 3)) * 80 + ((lane >> 3) & 1) * 16;

    for (int c = 0; c < 32; c++) {
        if (c <= 29)      { CP_WAIT(2); }
        else if (c == 30) { CP_WAIT(1); }
        else              { CP_WAIT(0); }
        __syncthreads();
        if (c + 3 < 32) { load_chunk(c + 3, (c + 3) & 3); CP_COMMIT(); }

        uint32 sa = base + (c & 3) * KV_STAGE_BYTES;
        uint32 sb = sa + KV_SA_BYTES;
#pragma unroll
        for (int ks = 0; ks < 2; ks++) {
            uint32 afr[4][4], bfr[8][2];
#pragma unroll
            for (int mi = 0; mi < 4; mi++)
                LDSM4(afr[mi][0], afr[mi][1], afr[mi][2], afr[mi][3],
                      sa + rowA_off + mi * 16 * 80 + ks * 32);
#pragma unroll
            for (int nj = 0; nj < 4; nj++)
                LDSM4(bfr[2 * nj][0], bfr[2 * nj][1], bfr[2 * nj + 1][0], bfr[2 * nj + 1][1],
                      sb + rowB_off + nj * 16 * 80 + ks * 32);
#pragma unroll
            for (int mi = 0; mi < 4; mi++)
#pragma unroll
                for (int ni = 0; ni < 8; ni++)
                    mma16816(acc[mi][ni], afr[mi], bfr[ni]);
        }
    }

    // epilogue: bias (+phi on k-half), bf16 store
    bool isk = (n0 < 1024);
    __nv_bfloat16* dst = isk ? g_pk : g_v;
    int cbase = isk ? n0 : (n0 - 1024);
#pragma unroll
    for (int mi = 0; mi < 4; mi++) {
        int r_lo = m0 + wm * 64 + mi * 16 + gid;
#pragma unroll
        for (int ni = 0; ni < 8; ni++) {
            int col = wn * 64 + ni * 8 + tig * 2;
            int ng = n0 + col;
            float b0 = g_bias2[ng], b1 = g_bias2[ng + 1];
            float v00 = acc[mi][ni][0] + b0, v01 = acc[mi][ni][1] + b1;
            float v10 = acc[mi][ni][2] + b0, v11 = acc[mi][ni][3] + b1;
            if (isk) { v00 = phi_f(v00); v01 = phi_f(v01); v10 = phi_f(v10); v11 = phi_f(v11); }
            __nv_bfloat162 p0, p1;
            p0.x = __float2bfloat16(v00); p0.y = __float2bfloat16(v01);
            p1.x = __float2bfloat16(v10); p1.y = __float2bfloat16(v11);
            *(__nv_bfloat162*)(dst + (size_t)r_lo * 1024 + cbase + col)       = p0;
            *(__nv_bfloat162*)(dst + (size_t)(r_lo + 8) * 1024 + cbase + col) = p1;
        }
    }
}

// ---------------- kv_state[b,h] = pk^T @ v ; ksum = colsum(pk) ----------------
__global__ void __launch_bounds__(128) kvstate_kernel() {
    __shared__ __nv_bfloat16 sPk[64][34];  // transposed: [dk][s]
    __shared__ __nv_bfloat16 sV [64][34];

    int tid = threadIdx.x;
    int bh = blockIdx.x;
    int bb = bh >> 4, h = bh & 15;
    int warp = tid >> 5, lane = tid & 31, gid = lane >> 2, tig = lane & 3;

    float acc[8][4];
#pragma unroll
    for (int ni = 0; ni < 8; ni++)
#pragma unroll
        for (int q = 0; q < 4; q++) acc[ni][q] = 0.f;
    float ksum = 0.f;

    size_t base = ((size_t)bb * 2048) * 1024 + h * 64;
    for (int sc = 0; sc < 2048; sc += 32) {
#pragma unroll
        for (int t = 0; t < 8; t++) {
            int i = tid + t * 128;          // 0..1023: pair loads
            int ss = i >> 5, j = i & 31;    // dk pair j -> dk = 2j
            size_t gi = base + (size_t)(sc + ss) * 1024 + 2 * j;
            __nv_bfloat162 pk2 = *(const __nv_bfloat162*)(g_pk + gi);
            __nv_bfloat162 v2  = *(const __nv_bfloat162*)(g_v + gi);
            sPk[2 * j][ss] = pk2.x; sPk[2 * j + 1][ss] = pk2.y;
            sV [2 * j][ss] = v2.x;  sV [2 * j + 1][ss] = v2.y;
        }
        __syncthreads();
        if (tid < 64) {
#pragma unroll
            for (int ss = 0; ss < 32; ss++) ksum += __bfloat162float(sPk[tid][ss]);
        }
#pragma unroll
        for (int ks = 0; ks < 32; ks += 16) {
            uint32 afr[4], bfr[8][2];
            int rr = warp * 16;
            afr[0] = *(uint32*)&sPk[rr + gid][ks + tig * 2];
            afr[1] = *(uint32*)&sPk[rr + gid + 8][ks + tig * 2];
            afr[2] = *(uint32*)&sPk[rr + gid][ks + tig * 2 + 8];
            afr[3] = *(uint32*)&sPk[rr + gid + 8][ks + tig * 2 + 8];
#pragma unroll
            for (int ni = 0; ni < 8; ni++) {
                bfr[ni][0] = *(uint32*)&sV[ni * 8 + gid][ks + tig * 2];
                bfr[ni][1] = *(uint32*)&sV[ni * 8 + gid][ks + tig * 2 + 8];
            }
#pragma unroll
            for (int ni = 0; ni < 8; ni++) mma16816(acc[ni], afr, bfr[ni]);
        }
        __syncthreads();
    }

    float* out = g_kvstate + (size_t)bh * 4096;
#pragma unroll
    for (int ni = 0; ni < 8; ni++) {
        int col = ni * 8 + tig * 2;
        int row = warp * 16 + gid;
        out[row * 64 + col]           = acc[ni][0];
        out[row * 64 + col + 1]       = acc[ni][1];
        out[(row + 8) * 64 + col]     = acc[ni][2];
        out[(row + 8) * 64 + col + 1] = acc[ni][3];
    }
    if (tid < 64) g_ksum[(size_t)bh * 64 + tid] = ksum;
}

// ---------------- attention readout (num/den) -> g_attn; copy zL into g_pre ----------------
__global__ void __launch_bounds__(256) attn_compute_kernel(const float* __restrict__ zL) {
    __shared__ float s_pq[1024];
    __shared__ float s_den[16];
    int bb = blockIdx.x, tid = threadIdx.x;

    for (int i = tid; i < 1024; i += 256) s_pq[i] = g_pq[bb * 1024 + i];
    __syncthreads();
    if (tid < 16) {
        const float* ks = g_ksum + ((size_t)bb * 16 + tid) * 64;
        float d = 0.f;
#pragma unroll 8
        for (int k = 0; k < 64; k++) d += s_pq[tid * 64 + k] * ks[k];
        s_den[tid] = d + 1e-6f;
    }
    __syncthreads();
#pragma unroll
    for (int j = 0; j < 4; j++) {
        int e = tid + j * 256;
        int h = e >> 6, dv = e & 63;
        const float* kvs = g_kvstate + (((size_t)bb * 16 + h) * 64) * 64 + dv;
        float num = 0.f;
#pragma unroll 8
        for (int dk = 0; dk < 64; dk++) num += s_pq[h * 64 + dk] * kvs[dk * 64];
        g_attn[(size_t)bb * 1024 + e] = num / s_den[h];
        g_pre[(size_t)bb * 2048 + 1024 + e] = zL[(size_t)bb * 1024 + e];
    }
}

// ---------------- trace shift + trace processor -> both outputs ----------------
__global__ void __launch_bounds__(256) trace_kernel(const float* __restrict__ zt,
                                                    const float* __restrict__ w1,
                                                    const float* __restrict__ b1,
                                                    const float* __restrict__ w2,
                                                    const float* __restrict__ b2p,
                                                    float* __restrict__ out) {
    __shared__ float sT[64][33];
    __shared__ float sW1[32][64];
    __shared__ float sB1[64];
    __shared__ float sW2[64];
    __shared__ float sRed[4][64];
    int tid = threadIdx.x;
    int r0 = blockIdx.x * 64;
    float* out_act = out;
    float* out_tr = out + BDIM * DDIM;

    for (int idx = tid; idx < 2048; idx += 256) {
        int rr = idx >> 5, mm = idx & 31;
        float v = (mm < 31) ? zt[(size_t)(r0 + rr) * 32 + mm + 1] : g_state[r0 + rr];
        sT[rr][mm] = v;
        out_tr[(size_t)(r0 + rr) * 32 + mm] = v;
    }
    for (int idx = tid; idx < 2048; idx += 256) {
        int m = idx >> 6, hh = idx & 63;
        sW1[m][hh] = w1[idx];
    }
    if (tid < 64) { sB1[tid] = b1[tid]; sW2[tid] = w2[tid]; }
    __syncthreads();

    int rr = tid & 63, part = tid >> 6;
    float acc = 0.f;
#pragma unroll
    for (int hi = 0; hi < 16; hi++) {
        int hh = part * 16 + hi;
        float hs = sB1[hh];
#pragma unroll
        for (int m = 0; m < 32; m++) hs += sT[rr][m] * sW1[m][hh];
        acc += fmaxf(hs, 0.f) * sW2[hh];
    }
    sRed[part][rr] = acc;
    __syncthreads();
    if (tid < 64)
        out_act[r0 + tid] = sRed[0][tid] + sRed[1][tid] + sRed[2][tid] + sRed[3][tid] + b2p[0];
}

// ---------------- launch ----------------
extern "C" void kernel_launch(void* const* d_in, const int* in_sizes, int n_in,
                              void* d_out, int out_size) {
    (void)in_sizes; (void)n_in; (void)out_size;
    const float* zL  = (const float*)d_in[0];
    const float* zt  = (const float*)d_in[1];
    const float* zH  = (const float*)d_in[2];
    const float* x   = (const float*)d_in[3];
    const float* sy  = (const float*)d_in[4];
    const float* qpw = (const float*)d_in[5];
    const float* qpb = (const float*)d_in[6];
    const float* wq  = (const float*)d_in[7];
    const float* bq  = (const float*)d_in[8];
    const float* wk  = (const float*)d_in[9];
    const float* bk  = (const float*)d_in[10];
    const float* wv  = (const float*)d_in[11];
    const float* bv  = (const float*)d_in[12];
    const float* wo  = (const float*)d_in[13];
    const float* bo  = (const float*)d_in[14];
    const float* sw1 = (const float*)d_in[15];
    const float* sb1 = (const float*)d_in[16];
    const float* sw2 = (const float*)d_in[17];
    const float* sb2 = (const float*)d_in[18];
    const float* tw1 = (const float*)d_in[19];
    const float* tb1 = (const float*)d_in[20];
    const float* tw2 = (const float*)d_in[21];
    const float* tb2 = (const float*)d_in[22];
    float* out = (float*)d_out;

    float *p_q, *p_pq, *p_pre, *p_hidden, *p_state, *p_attn, *p_partial;
    cudaGetSymbolAddress((void**)&p_q,       g_q);
    cudaGetSymbolAddress((void**)&p_pq,      g_pq);
    cudaGetSymbolAddress((void**)&p_pre,     g_pre);
    cudaGetSymbolAddress((void**)&p_hidden,  g_hidden);
    cudaGetSymbolAddress((void**)&p_state,   g_state);
    cudaGetSymbolAddress((void**)&p_attn,    g_attn);
    cudaGetSymbolAddress((void**)&p_partial, g_partial);   // <-- the R8/R9 bug: was host shadow

    cudaFuncSetAttribute(gemm_kv_mma_kernel,
                         cudaFuncAttributeMaxDynamicSharedMemorySize, KV_SMEM_BYTES);

    // weight prep
    pack_wT_kernel<<<dim3(64, 32), 256>>>(wk, wv);
    biases_kernel<<<8, 256>>>(bk, bv);
    convert_kv_kernel<<<131072, 256>>>(x, zH);

    // q path (split-K): q = sy@qp_w + qp_b ; pq = phi(q@wq + bq)
    gemm_splitk_kernel<<<dim3(16, 4), 256>>>(sy, SYNCD, 128, qpw, p_partial, 1024);
    reduce_act_kernel<<<256, 256>>>(p_partial, 4, qpb, p_q, 1024, 1024, 0);
    gemm_splitk_kernel<<<dim3(16, 8), 256>>>(p_q, 1024, 128, wq, p_partial, 1024);
    reduce_act_kernel<<<256, 256>>>(p_partial, 8, bq, p_pq, 1024, 1024, 2);

    // big K/V projection GEMM (pipelined HMMA, ldmatrix fragments)
    gemm_kv_mma_kernel<<<dim3(8, 1024), 256, KV_SMEM_BYTES>>>();

    // linear-attention state
    kvstate_kernel<<<1024, 128>>>();

    // attention readout -> g_attn, copy zL -> pre[:,1024:]
    attn_compute_kernel<<<64, 256>>>(zL);

    // attn_out = g_attn @ wo + bo -> pre[:,0:1024]
    gemm_splitk_kernel<<<dim3(16, 8), 256>>>(p_attn, 1024, 128, wo, p_partial, 1024);
    reduce_act_kernel<<<256, 256>>>(p_partial, 8, bo, p_pre, 1024, 2048, 0);

    // synapse MLP
    gemm_splitk_kernel<<<dim3(32, 8), 256>>>(p_pre, 2048, 256, sw1, p_partial, 2048);
    reduce_act_kernel<<<512, 256>>>(p_partial, 8, sb1, p_hidden, 2048, 2048, 1);
    gemm_splitk_kernel<<<dim3(16, 8), 256>>>(p_hidden, 2048, 256, sw2, p_partial, 1024);
    reduce_act_kernel<<<256, 256>>>(p_partial, 8, sb2, p_state, 1024, 1024, 0);

    // trace update + processor -> writes both outputs
    trace_kernel<<<1024, 256>>>(zt, tw1, tb1, tw2, tb2, out);
}

// round 11
// speedup vs baseline: 1.8502x; 1.0231x over previous
#include <cuda_runtime.h>
#include <cuda_bf16.h>
#include <cstdint>

// ---------------- problem dims ----------------
#define BDIM  64
#define SDIM  2048
#define EDIM  1024
#define DDIM  1024
#define SYNCD 512
#define MDIM  32
#define NHEADS 16
#define DH    64
#define SYNH  2048
#define TRH   64

typedef unsigned int uint32;

// ---------------- scratch (static device globals; no allocation) ----------------
__device__ __nv_bfloat16 g_kv  [(size_t)BDIM * SDIM * EDIM];  // x_context + zH, bf16
__device__ __nv_bfloat16 g_pk  [(size_t)BDIM * SDIM * EDIM];  // phi(k)
__device__ __nv_bfloat16 g_v   [(size_t)BDIM * SDIM * EDIM];  // v
__device__ __nv_bfloat16 g_wkvT[(size_t)2048 * EDIM];         // transposed: [n][k], n<1024 wk else wv
__device__ float g_bias2[2048];                               // bk | bv
__device__ float g_q    [BDIM * EDIM];
__device__ float g_pq   [BDIM * EDIM];
__device__ float g_kvstate[(size_t)BDIM * NHEADS * DH * DH];  // [b*16+h][dk][dv]
__device__ float g_ksum [BDIM * NHEADS * DH];
__device__ float g_attn [BDIM * EDIM];
__device__ float g_pre  [BDIM * 2048];                        // [attn_out | activated_zL]
__device__ float g_hidden[BDIM * SYNH];
__device__ float g_state[BDIM * DDIM];
__device__ float g_partial[(size_t)8 * 64 * 2048];            // split-K partials

// ---------------- helpers ----------------
__device__ __forceinline__ float phi_f(float x) { return x > 0.f ? x + 1.f : __expf(x); }

__device__ __forceinline__ uint32 smem_u32(const void* p) {
    return (uint32)__cvta_generic_to_shared(p);
}

#define CP_ASYNC16(dst, src) \
    asm volatile("cp.async.cg.shared.global [%0], [%1], 16;" :: "r"(dst), "l"(src) : "memory")
#define CP_COMMIT() asm volatile("cp.async.commit_group;" ::: "memory")
#define CP_WAIT(n)  asm volatile("cp.async.wait_group %0;" :: "n"(n) : "memory")

#define LDSM4(r0, r1, r2, r3, addr) \
    asm volatile("ldmatrix.sync.aligned.m8n8.x4.shared.b16 {%0,%1,%2,%3}, [%4];" \
                 : "=r"(r0), "=r"(r1), "=r"(r2), "=r"(r3) : "r"(addr))

__device__ __forceinline__ void mma16816(float* d, const uint32* a, const uint32* b) {
    asm volatile(
        "mma.sync.aligned.m16n8k16.row.col.f32.bf16.bf16.f32 "
        "{%0,%1,%2,%3},{%4,%5,%6,%7},{%8,%9},{%0,%1,%2,%3};\n"
        : "+f"(d[0]), "+f"(d[1]), "+f"(d[2]), "+f"(d[3])
        : "r"(a[0]), "r"(a[1]), "r"(a[2]), "r"(a[3]), "r"(b[0]), "r"(b[1]));
}

// ---------------- pack: transpose wk|wv -> g_wkvT[n][k] bf16 ----------------
__global__ void __launch_bounds__(256) pack_wT_kernel(const float* __restrict__ wk,
                                                      const float* __restrict__ wv) {
    __shared__ float tile[32][33];
    int tx = threadIdx.x & 31, ty = threadIdx.x >> 5;  // 32 x 8
    int n_glob0 = blockIdx.x * 32;
    int k0 = blockIdx.y * 32;
    const float* src = (n_glob0 < 1024) ? wk : wv;
    int ncol0 = (n_glob0 < 1024) ? n_glob0 : (n_glob0 - 1024);
#pragma unroll
    for (int j = 0; j < 32; j += 8) {
        int k = k0 + ty + j;
        tile[ty + j][tx] = src[(size_t)k * 1024 + ncol0 + tx];
    }
    __syncthreads();
#pragma unroll
    for (int j = 0; j < 32; j += 8) {
        int n = n_glob0 + ty + j;
        int k = k0 + tx;
        g_wkvT[(size_t)n * 1024 + k] = __float2bfloat16(tile[tx][ty + j]);
    }
}

__global__ void biases_kernel(const float* __restrict__ bk, const float* __restrict__ bv) {
    int i = blockIdx.x * blockDim.x + threadIdx.x;
    if (i < 2048) g_bias2[i] = (i < 1024) ? bk[i] : bv[i - 1024];
}

// ---------------- kv = x_context + zH -> bf16 ----------------
__global__ void convert_kv_kernel(const float* __restrict__ x, const float* __restrict__ zH) {
    size_t i4 = (size_t)blockIdx.x * blockDim.x + threadIdx.x;
    size_t e0 = i4 * 4;
    int e = (int)(e0 & 1023);
    int b = (int)(e0 >> 21);
    float4 xv = ((const float4*)x)[i4];
    float4 zv = *(const float4*)&zH[b * 1024 + e];
    __nv_bfloat162 lo, hi;
    lo.x = __float2bfloat16(xv.x + zv.x); lo.y = __float2bfloat16(xv.y + zv.y);
    hi.x = __float2bfloat16(xv.z + zv.z); hi.y = __float2bfloat16(xv.w + zv.w);
    ((__nv_bfloat162*)g_kv)[i4 * 2]     = lo;
    ((__nv_bfloat162*)g_kv)[i4 * 2 + 1] = hi;
}

// ---------------- split-K small GEMM: partial[split] = A[64][Kc-slice] @ W ----------------
__global__ void __launch_bounds__(256) gemm_splitk_kernel(
    const float* __restrict__ A, int K, int Kc,
    const float* __restrict__ W, float* __restrict__ partial, int N) {
    __shared__ float sA[64][33];
    __shared__ float sW[32][65];
    int tid = threadIdx.x;
    int g = tid >> 6, nn = tid & 63;
    int n0 = blockIdx.x * 64;
    int k0 = blockIdx.y * Kc;
    float acc[16];
#pragma unroll
    for (int i = 0; i < 16; i++) acc[i] = 0.f;

    for (int kc = k0; kc < k0 + Kc; kc += 32) {
        for (int idx = tid; idx < 2048; idx += 256) {
            int bb = idx >> 5, kk = idx & 31;
            sA[bb][kk] = A[(size_t)bb * K + kc + kk];
        }
        for (int idx = tid; idx < 2048; idx += 256) {
            int kk = idx >> 6, n_ = idx & 63;
            sW[kk][n_] = W[(size_t)(kc + kk) * N + n0 + n_];
        }
        __syncthreads();
#pragma unroll 8
        for (int kk = 0; kk < 32; kk++) {
            float w = sW[kk][nn];
#pragma unroll
            for (int bl = 0; bl < 16; bl++)
                acc[bl] += sA[g * 16 + bl][kk] * w;
        }
        __syncthreads();
    }
    float* out = partial + (size_t)blockIdx.y * 64 * N;
#pragma unroll
    for (int bl = 0; bl < 16; bl++)
        out[(size_t)(g * 16 + bl) * N + n0 + nn] = acc[bl];
}

// act: 0 none, 1 relu, 2 phi
__global__ void reduce_act_kernel(const float* __restrict__ partial, int nsplit,
                                  const float* __restrict__ bias,
                                  float* __restrict__ out, int N, int out_stride, int act) {
    int i = blockIdx.x * blockDim.x + threadIdx.x;
    if (i >= 64 * N) return;
    int b = i / N, n = i - b * N;
    float acc = bias ? bias[n] : 0.f;
    for (int s = 0; s < nsplit; s++) acc += partial[(size_t)s * 64 * N + i];
    if (act == 1) acc = fmaxf(acc, 0.f);
    else if (act == 2) acc = phi_f(acc);
    out[(size_t)b * out_stride + n] = acc;
}

// ---------------- big GEMM (pipelined HMMA): [phi(kv@wk+bk) | kv@wv+bv] ----------------
// CTA tile 128(M) x 256(N), k-chunks of 32, 4-stage cp.async, ldmatrix operands.
// 16 warps (512 threads), each computes 64x32 (warp grid 2M x 8N) -> 4 warps/SMSP.
#define KV_TM 128
#define KV_TN 256
#define KV_SA_BYTES (128 * 80)                 // row stride 80B = 32 bf16 + 16B pad
#define KV_SB_BYTES (256 * 80)
#define KV_STAGE_BYTES (KV_SA_BYTES + KV_SB_BYTES)   // 30720
#define KV_SMEM_BYTES (4 * KV_STAGE_BYTES)           // 122880

__global__ void __launch_bounds__(512, 1) gemm_kv_mma_kernel() {
    extern __shared__ char sm_raw[];
    uint32 base = smem_u32(sm_raw);
    int tid = threadIdx.x, warp = tid >> 5, lane = tid & 31;
    int gid = lane >> 2, tig = lane & 3;
    int wm = warp >> 3, wn = warp & 7;             // 2 x 8 warp grid, warp tile 64x32
    int n0 = blockIdx.x * KV_TN, m0 = blockIdx.y * KV_TM;

    const __nv_bfloat16* baseA = g_kv   + (size_t)m0 * 1024;
    const __nv_bfloat16* baseB = g_wkvT + (size_t)n0 * 1024;

    float acc[4][4][4];
#pragma unroll
    for (int mi = 0; mi < 4; mi++)
#pragma unroll
        for (int ni = 0; ni < 4; ni++)
#pragma unroll
            for (int q = 0; q < 4; q++) acc[mi][ni][q] = 0.f;

    auto load_chunk = [&](int c, int s) {
        uint32 sa = base + s * KV_STAGE_BYTES;
        uint32 sb = sa + KV_SA_BYTES;
        int kc = c * 32;
        {   // A: 512 x 16B
            int row = tid >> 2, seg = tid & 3;
            CP_ASYNC16(sa + row * 80 + seg * 16,
                       baseA + (size_t)row * 1024 + kc + seg * 8);
        }
#pragma unroll
        for (int t = 0; t < 2; t++) {              // B: 1024 x 16B
            int i = tid + t * 512;
            int row = i >> 2, seg = i & 3;
            CP_ASYNC16(sb + row * 80 + seg * 16,
                       baseB + (size_t)row * 1024 + kc + seg * 8);
        }
    };

    load_chunk(0, 0); CP_COMMIT();
    load_chunk(1, 1); CP_COMMIT();
    load_chunk(2, 2); CP_COMMIT();

    // ldmatrix per-lane address offsets (within a stage)
    int rowA_off = (wm * 64 + (lane & 15)) * 80 + (lane >> 4) * 16;
    int rowB_off = (wn * 32 + (lane & 7) + ((lane >> 4) << 3)) * 80 + ((lane >> 3) & 1) * 16;

    for (int c = 0; c < 32; c++) {
        if (c <= 29)      { CP_WAIT(2); }
        else if (c == 30) { CP_WAIT(1); }
        else              { CP_WAIT(0); }
        __syncthreads();
        if (c + 3 < 32) { load_chunk(c + 3, (c + 3) & 3); CP_COMMIT(); }

        uint32 sa = base + (c & 3) * KV_STAGE_BYTES;
        uint32 sb = sa + KV_SA_BYTES;
#pragma unroll
        for (int ks = 0; ks < 2; ks++) {
            uint32 afr[4][4], bfr[4][2];
#pragma unroll
            for (int mi = 0; mi < 4; mi++)
                LDSM4(afr[mi][0], afr[mi][1], afr[mi][2], afr[mi][3],
                      sa + rowA_off + mi * 16 * 80 + ks * 32);
#pragma unroll
            for (int nj = 0; nj < 2; nj++)
                LDSM4(bfr[2 * nj][0], bfr[2 * nj][1], bfr[2 * nj + 1][0], bfr[2 * nj + 1][1],
                      sb + rowB_off + nj * 16 * 80 + ks * 32);
#pragma unroll
            for (int mi = 0; mi < 4; mi++)
#pragma unroll
                for (int ni = 0; ni < 4; ni++)
                    mma16816(acc[mi][ni], afr[mi], bfr[ni]);
        }
    }

    // epilogue: bias (+phi on k-half), bf16 store
    bool isk = (n0 < 1024);
    __nv_bfloat16* dst = isk ? g_pk : g_v;
    int cbase = isk ? n0 : (n0 - 1024);
#pragma unroll
    for (int mi = 0; mi < 4; mi++) {
        int r_lo = m0 + wm * 64 + mi * 16 + gid;
#pragma unroll
        for (int ni = 0; ni < 4; ni++) {
            int col = wn * 32 + ni * 8 + tig * 2;
            int ng = n0 + col;
            float b0 = g_bias2[ng], b1 = g_bias2[ng + 1];
            float v00 = acc[mi][ni][0] + b0, v01 = acc[mi][ni][1] + b1;
            float v10 = acc[mi][ni][2] + b0, v11 = acc[mi][ni][3] + b1;
            if (isk) { v00 = phi_f(v00); v01 = phi_f(v01); v10 = phi_f(v10); v11 = phi_f(v11); }
            __nv_bfloat162 p0, p1;
            p0.x = __float2bfloat16(v00); p0.y = __float2bfloat16(v01);
            p1.x = __float2bfloat16(v10); p1.y = __float2bfloat16(v11);
            *(__nv_bfloat162*)(dst + (size_t)r_lo * 1024 + cbase + col)       = p0;
            *(__nv_bfloat162*)(dst + (size_t)(r_lo + 8) * 1024 + cbase + col) = p1;
        }
    }
}

// ---------------- kv_state[b,h] = pk^T @ v ; ksum = colsum(pk) ----------------
__global__ void __launch_bounds__(128) kvstate_kernel() {
    __shared__ __nv_bfloat16 sPk[64][34];  // transposed: [dk][s]
    __shared__ __nv_bfloat16 sV [64][34];

    int tid = threadIdx.x;
    int bh = blockIdx.x;
    int bb = bh >> 4, h = bh & 15;
    int warp = tid >> 5, lane = tid & 31, gid = lane >> 2, tig = lane & 3;

    float acc[8][4];
#pragma unroll
    for (int ni = 0; ni < 8; ni++)
#pragma unroll
        for (int q = 0; q < 4; q++) acc[ni][q] = 0.f;
    float ksum = 0.f;

    size_t base = ((size_t)bb * 2048) * 1024 + h * 64;
    for (int sc = 0; sc < 2048; sc += 32) {
#pragma unroll
        for (int t = 0; t < 8; t++) {
            int i = tid + t * 128;          // 0..1023: pair loads
            int ss = i >> 5, j = i & 31;    // dk pair j -> dk = 2j
            size_t gi = base + (size_t)(sc + ss) * 1024 + 2 * j;
            __nv_bfloat162 pk2 = *(const __nv_bfloat162*)(g_pk + gi);
            __nv_bfloat162 v2  = *(const __nv_bfloat162*)(g_v + gi);
            sPk[2 * j][ss] = pk2.x; sPk[2 * j + 1][ss] = pk2.y;
            sV [2 * j][ss] = v2.x;  sV [2 * j + 1][ss] = v2.y;
        }
        __syncthreads();
        if (tid < 64) {
#pragma unroll
            for (int ss = 0; ss < 32; ss++) ksum += __bfloat162float(sPk[tid][ss]);
        }
#pragma unroll
        for (int ks = 0; ks < 32; ks += 16) {
            uint32 afr[4], bfr[8][2];
            int rr = warp * 16;
            afr[0] = *(uint32*)&sPk[rr + gid][ks + tig * 2];
            afr[1] = *(uint32*)&sPk[rr + gid + 8][ks + tig * 2];
            afr[2] = *(uint32*)&sPk[rr + gid][ks + tig * 2 + 8];
            afr[3] = *(uint32*)&sPk[rr + gid + 8][ks + tig * 2 + 8];
#pragma unroll
            for (int ni = 0; ni < 8; ni++) {
                bfr[ni][0] = *(uint32*)&sV[ni * 8 + gid][ks + tig * 2];
                bfr[ni][1] = *(uint32*)&sV[ni * 8 + gid][ks + tig * 2 + 8];
            }
#pragma unroll
            for (int ni = 0; ni < 8; ni++) mma16816(acc[ni], afr, bfr[ni]);
        }
        __syncthreads();
    }

    float* out = g_kvstate + (size_t)bh * 4096;
#pragma unroll
    for (int ni = 0; ni < 8; ni++) {
        int col = ni * 8 + tig * 2;
        int row = warp * 16 + gid;
        out[row * 64 + col]           = acc[ni][0];
        out[row * 64 + col + 1]       = acc[ni][1];
        out[(row + 8) * 64 + col]     = acc[ni][2];
        out[(row + 8) * 64 + col + 1] = acc[ni][3];
    }
    if (tid < 64) g_ksum[(size_t)bh * 64 + tid] = ksum;
}

// ---------------- attention readout (num/den) -> g_attn; copy zL into g_pre ----------------
__global__ void __launch_bounds__(256) attn_compute_kernel(const float* __restrict__ zL) {
    __shared__ float s_pq[1024];
    __shared__ float s_den[16];
    int bb = blockIdx.x, tid = threadIdx.x;

    for (int i = tid; i < 1024; i += 256) s_pq[i] = g_pq[bb * 1024 + i];
    __syncthreads();
    if (tid < 16) {
        const float* ks = g_ksum + ((size_t)bb * 16 + tid) * 64;
        float d = 0.f;
#pragma unroll 8
        for (int k = 0; k < 64; k++) d += s_pq[tid * 64 + k] * ks[k];
        s_den[tid] = d + 1e-6f;
    }
    __syncthreads();
#pragma unroll
    for (int j = 0; j < 4; j++) {
        int e = tid + j * 256;
        int h = e >> 6, dv = e & 63;
        const float* kvs = g_kvstate + (((size_t)bb * 16 + h) * 64) * 64 + dv;
        float num = 0.f;
#pragma unroll 8
        for (int dk = 0; dk < 64; dk++) num += s_pq[h * 64 + dk] * kvs[dk * 64];
        g_attn[(size_t)bb * 1024 + e] = num / s_den[h];
        g_pre[(size_t)bb * 2048 + 1024 + e] = zL[(size_t)bb * 1024 + e];
    }
}

// ---------------- trace shift + trace processor -> both outputs ----------------
__global__ void __launch_bounds__(256) trace_kernel(const float* __restrict__ zt,
                                                    const float* __restrict__ w1,
                                                    const float* __restrict__ b1,
                                                    const float* __restrict__ w2,
                                                    const float* __restrict__ b2p,
                                                    float* __restrict__ out) {
    __shared__ float sT[64][33];
    __shared__ float sW1[32][64];
    __shared__ float sB1[64];
    __shared__ float sW2[64];
    __shared__ float sRed[4][64];
    int tid = threadIdx.x;
    int r0 = blockIdx.x * 64;
    float* out_act = out;
    float* out_tr = out + BDIM * DDIM;

    for (int idx = tid; idx < 2048; idx += 256) {
        int rr = idx >> 5, mm = idx & 31;
        float v = (mm < 31) ? zt[(size_t)(r0 + rr) * 32 + mm + 1] : g_state[r0 + rr];
        sT[rr][mm] = v;
        out_tr[(size_t)(r0 + rr) * 32 + mm] = v;
    }
    for (int idx = tid; idx < 2048; idx += 256) {
        int m = idx >> 6, hh = idx & 63;
        sW1[m][hh] = w1[idx];
    }
    if (tid < 64) { sB1[tid] = b1[tid]; sW2[tid] = w2[tid]; }
    __syncthreads();

    int rr = tid & 63, part = tid >> 6;
    float acc = 0.f;
#pragma unroll
    for (int hi = 0; hi < 16; hi++) {
        int hh = part * 16 + hi;
        float hs = sB1[hh];
#pragma unroll
        for (int m = 0; m < 32; m++) hs += sT[rr][m] * sW1[m][hh];
        acc += fmaxf(hs, 0.f) * sW2[hh];
    }
    sRed[part][rr] = acc;
    __syncthreads();
    if (tid < 64)
        out_act[r0 + tid] = sRed[0][tid] + sRed[1][tid] + sRed[2][tid] + sRed[3][tid] + b2p[0];
}

// ---------------- launch ----------------
extern "C" void kernel_launch(void* const* d_in, const int* in_sizes, int n_in,
                              void* d_out, int out_size) {
    (void)in_sizes; (void)n_in; (void)out_size;
    const float* zL  = (const float*)d_in[0];
    const float* zt  = (const float*)d_in[1];
    const float* zH  = (const float*)d_in[2];
    const float* x   = (const float*)d_in[3];
    const float* sy  = (const float*)d_in[4];
    const float* qpw = (const float*)d_in[5];
    const float* qpb = (const float*)d_in[6];
    const float* wq  = (const float*)d_in[7];
    const float* bq  = (const float*)d_in[8];
    const float* wk  = (const float*)d_in[9];
    const float* bk  = (const float*)d_in[10];
    const float* wv  = (const float*)d_in[11];
    const float* bv  = (const float*)d_in[12];
    const float* wo  = (const float*)d_in[13];
    const float* bo  = (const float*)d_in[14];
    const float* sw1 = (const float*)d_in[15];
    const float* sb1 = (const float*)d_in[16];
    const float* sw2 = (const float*)d_in[17];
    const float* sb2 = (const float*)d_in[18];
    const float* tw1 = (const float*)d_in[19];
    const float* tb1 = (const float*)d_in[20];
    const float* tw2 = (const float*)d_in[21];
    const float* tb2 = (const float*)d_in[22];
    float* out = (float*)d_out;

    float *p_q, *p_pq, *p_pre, *p_hidden, *p_state, *p_attn, *p_partial;
    cudaGetSymbolAddress((void**)&p_q,       g_q);
    cudaGetSymbolAddress((void**)&p_pq,      g_pq);
    cudaGetSymbolAddress((void**)&p_pre,     g_pre);
    cudaGetSymbolAddress((void**)&p_hidden,  g_hidden);
    cudaGetSymbolAddress((void**)&p_state,   g_state);
    cudaGetSymbolAddress((void**)&p_attn,    g_attn);
    cudaGetSymbolAddress((void**)&p_partial, g_partial);

    cudaFuncSetAttribute(gemm_kv_mma_kernel,
                         cudaFuncAttributeMaxDynamicSharedMemorySize, KV_SMEM_BYTES);

    // weight prep
    pack_wT_kernel<<<dim3(64, 32), 256>>>(wk, wv);
    biases_kernel<<<8, 256>>>(bk, bv);
    convert_kv_kernel<<<131072, 256>>>(x, zH);

    // q path (split-K): q = sy@qp_w + qp_b ; pq = phi(q@wq + bq)
    gemm_splitk_kernel<<<dim3(16, 4), 256>>>(sy, SYNCD, 128, qpw, p_partial, 1024);
    reduce_act_kernel<<<256, 256>>>(p_partial, 4, qpb, p_q, 1024, 1024, 0);
    gemm_splitk_kernel<<<dim3(16, 8), 256>>>(p_q, 1024, 128, wq, p_partial, 1024);
    reduce_act_kernel<<<256, 256>>>(p_partial, 8, bq, p_pq, 1024, 1024, 2);

    // big K/V projection GEMM (pipelined HMMA, 16 warps)
    gemm_kv_mma_kernel<<<dim3(8, 1024), 512, KV_SMEM_BYTES>>>();

    // linear-attention state
    kvstate_kernel<<<1024, 128>>>();

    // attention readout -> g_attn, copy zL -> pre[:,1024:]
    attn_compute_kernel<<<64, 256>>>(zL);

    // attn_out = g_attn @ wo + bo -> pre[:,0:1024]
    gemm_splitk_kernel<<<dim3(16, 8), 256>>>(p_attn, 1024, 128, wo, p_partial, 1024);
    reduce_act_kernel<<<256, 256>>>(p_partial, 8, bo, p_pre, 1024, 2048, 0);

    // synapse MLP
    gemm_splitk_kernel<<<dim3(32, 8), 256>>>(p_pre, 2048, 256, sw1, p_partial, 2048);
    reduce_act_kernel<<<512, 256>>>(p_partial, 8, sb1, p_hidden, 2048, 2048, 1);
    gemm_splitk_kernel<<<dim3(16, 8), 256>>>(p_hidden, 2048, 256, sw2, p_partial, 1024);
    reduce_act_kernel<<<256, 256>>>(p_partial, 8, sb2, p_state, 1024, 1024, 0);

    // trace update + processor -> writes both outputs
    trace_kernel<<<1024, 256>>>(zt, tw1, tb1, tw2, tb2, out);
}